// round 12
// baseline (speedup 1.0000x reference)
#include <cuda_runtime.h>
#include <cstdint>
#include <cstddef>

// Problem constants
#define NN 512
#define SD 256
#define ND 128
#define ED 16
#define CH 128              // i's per chunk in k_agg
#define NCH2 (NN / CH)      // 4 chunks
#define TT 32               // weight-tile rows for cp.async GEMMs

// ---------------- scratch (static device globals; no allocation) ----------------
__device__ float g_ef[NN * NN * ED];        // edge features, natural: [j][i][t] (16.7 MB)
__device__ float g_n[NN * ND];              // node features after projector+LN
__device__ float g_n2[NN * ND];             // node features after MPN layer 1
__device__ float g_A[NN * ND];              // n @ mW_src
__device__ float g_B[NN * ND];              // n @ mW_dst + mb
__device__ float g_aggp[NCH2][NN * ND];     // partial aggregated messages (per i-chunk)
__device__ float g_P[NN * 64];              // n @ Wc1[:128]
__device__ float g_Q[NN * 64];              // n @ Wc1[128:] + bc1

// ---------------- packed f32x2 helpers ----------------
__device__ __forceinline__ unsigned long long pack2(float lo, float hi) {
    unsigned long long r;
    asm("mov.b64 %0, {%1, %2};" : "=l"(r) : "f"(lo), "f"(hi));
    return r;
}
__device__ __forceinline__ void unpack2(unsigned long long v, float& lo, float& hi) {
    asm("mov.b64 {%0, %1}, %2;" : "=f"(lo), "=f"(hi) : "l"(v));
}
__device__ __forceinline__ unsigned long long fma2(unsigned long long a,
                                                   unsigned long long b,
                                                   unsigned long long c) {
    unsigned long long d;
    asm("fma.rn.f32x2 %0, %1, %2, %3;" : "=l"(d) : "l"(a), "l"(b), "l"(c));
    return d;
}
__device__ __forceinline__ float tanh_fast(float x) {
    float y;
    asm("tanh.approx.f32 %0, %1;" : "=f"(y) : "f"(x));
    return y;
}

// ---------------- cp.async helpers ----------------
__device__ __forceinline__ uint32_t smem_u32(const void* p) {
    return (uint32_t)__cvta_generic_to_shared(p);
}
__device__ __forceinline__ void cp16(uint32_t s, const void* g) {
    asm volatile("cp.async.cg.shared.global [%0], [%1], 16;" :: "r"(s), "l"(g));
}
__device__ __forceinline__ void cp_commit() {
    asm volatile("cp.async.commit_group;" ::: "memory");
}
__device__ __forceinline__ void cp_wait0() {
    asm volatile("cp.async.wait_group 0;" ::: "memory");
}
__device__ __forceinline__ void cp_wait1() {
    asm volatile("cp.async.wait_group 1;" ::: "memory");
}

// stage one TT x C weight tile into smem buffer (NTHR threads, float4 chunks)
template<int C, int NTHR>
__device__ __forceinline__ void stage_tile(float* buf, const float* __restrict__ W,
                                           int tile, int tid) {
    const float* src = W + (size_t)tile * TT * C;
    uint32_t b = smem_u32(buf);
    constexpr int NV = TT * C / 4;          // float4s per tile
#pragma unroll
    for (int r = 0; r < NV / NTHR; r++) {
        int idx = tid + NTHR * r;
        cp16(b + idx * 16, src + idx * 4);
    }
    cp_commit();
}

// ---------------- K1 (fused): node projector+LN+AB1  |  edge encoder ----------------
// 256 threads. blocks [0,256): node path (NB=2). blocks [256,768): edge, j = bx-256.
__global__ __launch_bounds__(256) void k_pre(
    const float* __restrict__ X,
    const float* __restrict__ W1, const float* __restrict__ b1,
    const float* __restrict__ W2, const float* __restrict__ b2,
    const float* __restrict__ lng, const float* __restrict__ lnb,
    const float* __restrict__ pos,
    const float* __restrict__ We1, const float* __restrict__ be1,
    const float* __restrict__ We2, const float* __restrict__ be2,
    const float* __restrict__ mW, const float* __restrict__ mb)
{
    const int tid = threadIdx.x;
    if (blockIdx.x < 256) {
        __shared__ float xs[2][SD];
        __shared__ float h1[2][ND];
        __shared__ float xs2[2][ND];
        __shared__ __align__(16) float wt[2][TT * ND];
        __shared__ float ssum[2][4], ssq[2][4];

        const int nd = tid >> 7;
        const int k  = tid & 127;
        const int n0 = blockIdx.x * 2;

        for (int idx = tid; idx < 2 * SD; idx += 256)
            xs[idx >> 8][idx & 255] = X[n0 * SD + idx];

        // ---- GEMM1: h1 = relu(xs @ W1 + b1), 8 tiles of 32x128 ----
        stage_tile<ND, 256>(wt[0], W1, 0, tid);
        stage_tile<ND, 256>(wt[1], W1, 1, tid);
        float acc = 0.f;
#pragma unroll
        for (int tile = 0; tile < 8; tile++) {
            const int buf = tile & 1;
            if (tile == 7) cp_wait0(); else cp_wait1();
            __syncthreads();
#pragma unroll
            for (int tt = 0; tt < TT; tt++)
                acc += xs[nd][tile * TT + tt] * wt[buf][tt * ND + k];
            if (tile + 2 < 8) {
                __syncthreads();
                stage_tile<ND, 256>(wt[buf], W1, tile + 2, tid);
            }
        }
        h1[nd][k] = fmaxf(acc + b1[k], 0.f);

        // ---- GEMM2: acc = h1 @ W2 + b2, 4 tiles of 32x128 ----
        stage_tile<ND, 256>(wt[0], W2, 0, tid);
        stage_tile<ND, 256>(wt[1], W2, 1, tid);
        acc = 0.f;
#pragma unroll
        for (int tile = 0; tile < 4; tile++) {
            const int buf = tile & 1;
            if (tile == 3) cp_wait0(); else cp_wait1();
            __syncthreads();          // also orders h1 writes before reads (tile 0)
#pragma unroll
            for (int tt = 0; tt < TT; tt++)
                acc += h1[nd][tile * TT + tt] * wt[buf][tt * ND + k];
            if (tile + 2 < 4) {
                __syncthreads();
                stage_tile<ND, 256>(wt[buf], W2, tile + 2, tid);
            }
        }
        acc += b2[k];

        // wt[0] free (last read at tile 2, barrier passed): prefetch AB tile 0 now
        stage_tile<ND, 256>(wt[0], mW, 0, tid);

        // ---- LayerNorm ----
        const int w4 = (tid >> 5) & 3, lane = tid & 31;
        {
            float v = acc, v2 = v * v;
            for (int o = 16; o > 0; o >>= 1) {
                v  += __shfl_xor_sync(0xffffffffu, v,  o);
                v2 += __shfl_xor_sync(0xffffffffu, v2, o);
            }
            if (lane == 0) { ssum[nd][w4] = v; ssq[nd][w4] = v2; }
        }
        __syncthreads();              // ssum ready; also all reads of wt[1] done
        stage_tile<ND, 256>(wt[1], mW, 1, tid);
        float s = ssum[nd][0] + ssum[nd][1] + ssum[nd][2] + ssum[nd][3];
        float q = ssq[nd][0] + ssq[nd][1] + ssq[nd][2] + ssq[nd][3];
        float mu = s * (1.0f / ND);
        float var = q * (1.0f / ND) - mu * mu;
        float r = rsqrtf(var + 1e-5f);
        float nval = (acc - mu) * r * lng[k] + lnb[k];
        g_n[(n0 + nd) * ND + k] = nval;
        xs2[nd][k] = nval;

        // ---- AB1: A = n@mW[:128], B = n@mW[128:256] + mb, 8 tiles ----
        float accA = 0.f, accB = 0.f;
#pragma unroll
        for (int tile = 0; tile < 8; tile++) {
            const int buf = tile & 1;
            if (tile == 7) cp_wait0(); else cp_wait1();
            __syncthreads();          // tile 0: also publishes xs2
            if (tile < 4) {
#pragma unroll
                for (int tt = 0; tt < TT; tt++)
                    accA += xs2[nd][tile * TT + tt] * wt[buf][tt * ND + k];
            } else {
#pragma unroll
                for (int tt = 0; tt < TT; tt++)
                    accB += xs2[nd][(tile - 4) * TT + tt] * wt[buf][tt * ND + k];
            }
            if (tile + 2 < 8) {
                __syncthreads();
                stage_tile<ND, 256>(wt[buf], mW, tile + 2, tid);
            }
        }
        g_A[(n0 + nd) * ND + k] = accA;
        g_B[(n0 + nd) * ND + k] = accB + mb[k];
    } else {
        // ---- edge encoder: writes natural [j][i][t] layout ----
        __shared__ float w1s[64], b1s[16], w2s[256], b2s[16];
        if (tid < 64) w1s[tid] = We1[tid];
        if (tid < 256) w2s[tid] = We2[tid];
        if (tid < 16) { b1s[tid] = be1[tid]; b2s[tid] = be2[tid]; }

        const int j = blockIdx.x - 256;
        const float pjx = pos[j * 2], pjy = pos[j * 2 + 1];
        __syncthreads();

        for (int i = tid; i < NN; i += 256) {
            float4* o4 = (float4*)&g_ef[((size_t)j * NN + i) * ED];
            if (i == j) {
                float4 z = make_float4(0.f, 0.f, 0.f, 0.f);
#pragma unroll
                for (int r = 0; r < 4; r++) o4[r] = z;
                continue;
            }
            const float pix = pos[i * 2], piy = pos[i * 2 + 1];
            const float dx = pjx - pix, dy = pjy - piy;
            const float dist = sqrtf(dx * dx + dy * dy);
            const float ang = atan2f(dy, dx);
            float h[16];
#pragma unroll
            for (int u = 0; u < 16; u++) {
                float a = pix * w1s[u] + piy * w1s[16 + u] + dist * w1s[32 + u]
                        + ang * w1s[48 + u] + b1s[u];
                h[u] = fmaxf(a, 0.f);
            }
            float o[16];
#pragma unroll
            for (int v = 0; v < 16; v++) {
                float a = b2s[v];
#pragma unroll
                for (int u = 0; u < 16; u++) a += h[u] * w2s[u * 16 + v];
                o[v] = tanh_fast(a);
            }
            o4[0] = make_float4(o[0], o[1], o[2], o[3]);
            o4[1] = make_float4(o[4], o[5], o[6], o[7]);
            o4[2] = make_float4(o[8], o[9], o[10], o[11]);
            o4[3] = make_float4(o[12], o[13], o[14], o[15]);
        }
    }
}

// ---------------- K4: fused ef-matvec + relu + segment-sum (partial) ----------------
// block = 128 threads = 2 dst j's (64 threads each); thread owns feature pair
// (2u, 2u+1), one even/odd-t packed chain per feature. ef staged through smem.
// CH=128 i's per chunk; no i!=j predicate in the loop — the spurious i==j term
// equals relu(A[j,f]+B[j,f]) exactly (ef[j,j]=0) and is subtracted afterwards.
// grid = (256 j-pairs, NCH2 i-chunks).
__global__ __launch_bounds__(128) void k_agg(const float* __restrict__ mW)
{
    __shared__ __align__(16) float efs[2][CH * ED];   // 2 x 8 KB

    const int grp = threadIdx.x >> 6;       // j within pair
    const int u   = threadIdx.x & 63;       // feature-pair index
    const int j  = blockIdx.x * 2 + grp;
    const int i0 = blockIdx.y * CH;
    const int f  = 2 * u;

    // W pairs: W0[s] = (w[2s][f], w[2s+1][f]),  W1[s] = same for f+1
    unsigned long long W0[8], W1[8];
#pragma unroll
    for (int s = 0; s < 8; s++) {
        W0[s] = pack2(mW[(2 * ND + 2 * s) * ND + f],
                      mW[(2 * ND + 2 * s + 1) * ND + f]);
        W1[s] = pack2(mW[(2 * ND + 2 * s) * ND + f + 1],
                      mW[(2 * ND + 2 * s + 1) * ND + f + 1]);
    }
    const float B0 = g_B[j * ND + f];
    const float B1 = g_B[j * ND + f + 1];

    // stage this group's CH i's of ef (8 KB) — coalesced bulk copy, high MLP
    {
        const float4* src = (const float4*)&g_ef[((size_t)j * NN + i0) * ED];
        float4* dst = (float4*)efs[grp];
#pragma unroll
        for (int r = 0; r < 8; r++)
            dst[u + 64 * r] = src[u + 64 * r];
    }
    __syncthreads();

    float acc0 = 0.f, acc1 = 0.f;
#pragma unroll 2
    for (int ii = 0; ii < CH; ii++) {
        const int i = i0 + ii;
        float2 a = *(const float2*)&g_A[i * ND + f];
        const ulonglong2* ep = (const ulonglong2*)&efs[grp][ii * ED];
        ulonglong2 q0 = ep[0], q1 = ep[1], q2 = ep[2], q3 = ep[3];

        unsigned long long c0 = pack2(a.x + B0, 0.f);
        unsigned long long c1 = pack2(a.y + B1, 0.f);
        c0 = fma2(q0.x, W0[0], c0);  c1 = fma2(q0.x, W1[0], c1);
        c0 = fma2(q0.y, W0[1], c0);  c1 = fma2(q0.y, W1[1], c1);
        c0 = fma2(q1.x, W0[2], c0);  c1 = fma2(q1.x, W1[2], c1);
        c0 = fma2(q1.y, W0[3], c0);  c1 = fma2(q1.y, W1[3], c1);
        c0 = fma2(q2.x, W0[4], c0);  c1 = fma2(q2.x, W1[4], c1);
        c0 = fma2(q2.y, W0[5], c0);  c1 = fma2(q2.y, W1[5], c1);
        c0 = fma2(q3.x, W0[6], c0);  c1 = fma2(q3.x, W1[6], c1);
        c0 = fma2(q3.y, W0[7], c0);  c1 = fma2(q3.y, W1[7], c1);

        float l0, h0, l1, h1;
        unpack2(c0, l0, h0);
        unpack2(c1, l1, h1);
        acc0 += fmaxf(l0 + h0, 0.f);
        acc1 += fmaxf(l1 + h1, 0.f);
    }

    // remove the spurious i==j contribution (exactly relu(A[j]+B[j]))
    if (j >= i0 && j < i0 + CH) {
        float2 aj = *(const float2*)&g_A[j * ND + f];
        acc0 -= fmaxf(aj.x + B0, 0.f);
        acc1 -= fmaxf(aj.y + B1, 0.f);
    }
    *(float2*)&g_aggp[blockIdx.y][j * ND + f] = make_float2(acc0, acc1);
}

// ---------------- K5a: upd (layer 1) fused with AB2 ----------------
// 512 threads, NB=4 nodes/block, 128 blocks.
__global__ __launch_bounds__(512) void k_upd_ab(
    const float* __restrict__ nin,
    const float* __restrict__ uW, const float* __restrict__ ub,
    float* __restrict__ nout,
    const float* __restrict__ mW, const float* __restrict__ mb)
{
    __shared__ float xs[4][2 * ND];
    __shared__ float xs2[4][ND];
    __shared__ __align__(16) float wt[2][TT * ND];
    const int tid = threadIdx.x;
    const int nd = tid >> 7;
    const int k  = tid & 127;
    const int n0 = blockIdx.x * 4;

    {
        int off = (n0 + nd) * ND + k;
        float s = g_aggp[0][off];
#pragma unroll
        for (int c = 1; c < NCH2; c++) s += g_aggp[c][off];
        xs[nd][k]      = nin[off];
        xs[nd][ND + k] = s;
    }

    stage_tile<ND, 512>(wt[0], uW, 0, tid);
    stage_tile<ND, 512>(wt[1], uW, 1, tid);

    float acc = 0.f;
#pragma unroll
    for (int tile = 0; tile < 8; tile++) {
        const int buf = tile & 1;
        if (tile == 7) cp_wait0(); else cp_wait1();
        __syncthreads();
#pragma unroll
        for (int tt = 0; tt < TT; tt++)
            acc += xs[nd][tile * TT + tt] * wt[buf][tt * ND + k];
        if (tile + 2 < 8) {
            __syncthreads();
            stage_tile<ND, 512>(wt[buf], uW, tile + 2, tid);
        }
    }
    float nval = fmaxf(acc + ub[k], 0.f);
    nout[(n0 + nd) * ND + k] = nval;
    xs2[nd][k] = nval;

    // wt[0] free (last read tile 6, barrier passed at tile 7's top)
    stage_tile<ND, 512>(wt[0], mW, 0, tid);
    __syncthreads();                       // all done reading wt[1]; xs2 published
    stage_tile<ND, 512>(wt[1], mW, 1, tid);

    // ---- AB2 ----
    float accA = 0.f, accB = 0.f;
#pragma unroll
    for (int tile = 0; tile < 8; tile++) {
        const int buf = tile & 1;
        if (tile == 7) cp_wait0(); else cp_wait1();
        __syncthreads();
        if (tile < 4) {
#pragma unroll
            for (int tt = 0; tt < TT; tt++)
                accA += xs2[nd][tile * TT + tt] * wt[buf][tt * ND + k];
        } else {
#pragma unroll
            for (int tt = 0; tt < TT; tt++)
                accB += xs2[nd][(tile - 4) * TT + tt] * wt[buf][tt * ND + k];
        }
        if (tile + 2 < 8) {
            __syncthreads();
            stage_tile<ND, 512>(wt[buf], mW, tile + 2, tid);
        }
    }
    g_A[(n0 + nd) * ND + k] = accA;
    g_B[(n0 + nd) * ND + k] = accB + mb[k];
}

// ---------------- K5b: upd (layer 2) fused with P/Q classifier GEMM ----------------
// 512 threads, NB=4 nodes/block, 128 blocks. P/Q tiles staged as pairs so both
// thread-halves stay busy.
__global__ __launch_bounds__(512) void k_upd_pq(
    const float* __restrict__ nin,
    const float* __restrict__ uW, const float* __restrict__ ub,
    float* __restrict__ nout,
    const float* __restrict__ Wc1, const float* __restrict__ bc1)
{
    __shared__ float xs[4][2 * ND];
    __shared__ float xs2[4][ND];
    __shared__ __align__(16) float wt[2][TT * ND];   // reused as [2][2][TT*64] for PQ
    const int tid = threadIdx.x;
    const int nd = tid >> 7;
    const int k  = tid & 127;
    const int n0 = blockIdx.x * 4;

    {
        int off = (n0 + nd) * ND + k;
        float s = g_aggp[0][off];
#pragma unroll
        for (int c = 1; c < NCH2; c++) s += g_aggp[c][off];
        xs[nd][k]      = nin[off];
        xs[nd][ND + k] = s;
    }

    stage_tile<ND, 512>(wt[0], uW, 0, tid);
    stage_tile<ND, 512>(wt[1], uW, 1, tid);

    float acc = 0.f;
#pragma unroll
    for (int tile = 0; tile < 8; tile++) {
        const int buf = tile & 1;
        if (tile == 7) cp_wait0(); else cp_wait1();
        __syncthreads();
#pragma unroll
        for (int tt = 0; tt < TT; tt++)
            acc += xs[nd][tile * TT + tt] * wt[buf][tt * ND + k];
        if (tile + 2 < 8) {
            __syncthreads();
            stage_tile<ND, 512>(wt[buf], uW, tile + 2, tid);
        }
    }
    float nval = fmaxf(acc + ub[k], 0.f);
    nout[(n0 + nd) * ND + k] = nval;
    xs2[nd][k] = nval;

    // ---- PQ: stage P-tile + Q-tile pairs (16KB each phase, 4 phases) ----
    {
        uint32_t b0 = smem_u32(wt[0]);
        cp16(b0 + tid * 16, Wc1 + 0 * TT * 64 + tid * 4);                 // P rows 0-31
        cp16(b0 + 8192 + tid * 16, Wc1 + (128 + 0 * TT) * 64 + tid * 4);  // Q rows 128-159
        cp_commit();
    }
    __syncthreads();                       // wt[1] free; xs2 published
    {
        uint32_t b1 = smem_u32(wt[1]);
        cp16(b1 + tid * 16, Wc1 + 1 * TT * 64 + tid * 4);
        cp16(b1 + 8192 + tid * 16, Wc1 + (128 + 1 * TT) * 64 + tid * 4);
        cp_commit();
    }

    const int half = (k >> 6);             // 0 -> P, 1 -> Q
    const int k64  = k & 63;
    float accPQ = 0.f;
#pragma unroll
    for (int phase = 0; phase < 4; phase++) {
        const int buf = phase & 1;
        if (phase == 3) cp_wait0(); else cp_wait1();
        __syncthreads();
        const float* w = &wt[buf][half * 2048];
#pragma unroll
        for (int tt = 0; tt < TT; tt++)
            accPQ += xs2[nd][phase * TT + tt] * w[tt * 64 + k64];
        if (phase + 2 < 4) {
            __syncthreads();
            uint32_t b = smem_u32(wt[buf]);
            cp16(b + tid * 16, Wc1 + (phase + 2) * TT * 64 + tid * 4);
            cp16(b + 8192 + tid * 16, Wc1 + (128 + (phase + 2) * TT) * 64 + tid * 4);
            cp_commit();
        }
    }
    if (half) g_Q[(n0 + nd) * 64 + k64] = accPQ + bc1[k64];
    else      g_P[(n0 + nd) * 64 + k64] = accPQ;
}

// ---------------- K7: pairwise scores (relu(P_i+Q_j) @ Wc2 -> sigmoid) ----------------
__global__ __launch_bounds__(256) void k_scores(
    const float* __restrict__ Wc2, const float* __restrict__ bc2,
    float* __restrict__ out)
{
    __shared__ float Ps[16][65], Qs[16][65], ws[64];
    const int tid = threadIdx.x;
    const int tx = tid & 15, ty = tid >> 4;
    const int j0 = blockIdx.x * 16, i0 = blockIdx.y * 16;

    for (int idx = tid; idx < 16 * 64; idx += 256) {
        int r = idx >> 6, c = idx & 63;
        Ps[r][c] = g_P[(i0 + r) * 64 + c];
        Qs[r][c] = g_Q[(j0 + r) * 64 + c];
    }
    if (tid < 64) ws[tid] = Wc2[tid];
    __syncthreads();

    float acc = 0.f;
#pragma unroll 8
    for (int t = 0; t < 64; t++)
        acc += fmaxf(Ps[ty][t] + Qs[tx][t], 0.f) * ws[t];
    acc += bc2[0];
    float s = 1.f / (1.f + expf(-acc));
    const int i = i0 + ty, j = j0 + tx;
    out[i * NN + j] = (i == j) ? 0.f : s;
}

// ---------------- launch ----------------
extern "C" void kernel_launch(void* const* d_in, const int* in_sizes, int n_in,
                              void* d_out, int out_size)
{
    const float* X   = (const float*)d_in[0];
    const float* pos = (const float*)d_in[1];
    const float* W1  = (const float*)d_in[2];
    const float* b1  = (const float*)d_in[3];
    const float* W2  = (const float*)d_in[4];
    const float* b2  = (const float*)d_in[5];
    const float* lng = (const float*)d_in[6];
    const float* lnb = (const float*)d_in[7];
    const float* We1 = (const float*)d_in[8];
    const float* be1 = (const float*)d_in[9];
    const float* We2 = (const float*)d_in[10];
    const float* be2 = (const float*)d_in[11];
    const float* mW1 = (const float*)d_in[12];
    const float* mb1 = (const float*)d_in[13];
    const float* uW1 = (const float*)d_in[14];
    const float* ub1 = (const float*)d_in[15];
    const float* mW2 = (const float*)d_in[16];
    const float* mb2 = (const float*)d_in[17];
    const float* uW2 = (const float*)d_in[18];
    const float* ub2 = (const float*)d_in[19];
    const float* Wc1 = (const float*)d_in[20];
    const float* bc1 = (const float*)d_in[21];
    const float* Wc2 = (const float*)d_in[22];
    const float* bc2 = (const float*)d_in[23];

    float* out   = (float*)d_out;
    float* out_n = out;             // [512*128] node features
    float* out_s = out + NN * ND;   // [512*512] scores

    float *pN = nullptr, *pN2 = nullptr;
    cudaGetSymbolAddress((void**)&pN,  g_n);
    cudaGetSymbolAddress((void**)&pN2, g_n2);

    // node projector+LN+AB1 (blocks 0..255) + edge encoder (blocks 256..767)
    k_pre<<<768, 256>>>(X, W1, b1, W2, b2, lng, lnb,
                        pos, We1, be1, We2, be2, mW1, mb1);

    // MPN layer 1 (agg) then fused update+AB2
    k_agg<<<dim3(256, NCH2), 128>>>(mW1);
    k_upd_ab<<<128, 512>>>(pN, uW1, ub1, pN2, mW2, mb2);

    // MPN layer 2 (agg) then fused update+PQ (final node features -> d_out)
    k_agg<<<dim3(256, NCH2), 128>>>(mW2);
    k_upd_pq<<<128, 512>>>(pN2, uW2, ub2, out_n, Wc1, bc1);

    // pairwise scores
    k_scores<<<dim3(32, 32), 256>>>(Wc2, bc2, out_s);
}

// round 13
// speedup vs baseline: 1.0491x; 1.0491x over previous
#include <cuda_runtime.h>
#include <cstdint>
#include <cstddef>

// Problem constants
#define NN 512
#define SD 256
#define ND 128
#define ED 16
#define CH 64               // i's per chunk in k_agg
#define NCH2 (NN / CH)      // 8 chunks
#define TT 32               // weight-tile rows for cp.async GEMMs

// ---------------- scratch (static device globals; no allocation) ----------------
__device__ float g_ef[NN * NN * ED];        // edge features, natural: [j][i][t] (16.7 MB)
__device__ float g_n[NN * ND];              // node features after projector+LN
__device__ float g_n2[NN * ND];             // node features after MPN layer 1
__device__ float g_A[NN * ND];              // n @ mW_src
__device__ float g_B[NN * ND];              // n @ mW_dst + mb
__device__ float g_aggp[NCH2][NN * ND];     // partial aggregated messages (per i-chunk)
__device__ float g_P[NN * 64];              // n @ Wc1[:128]
__device__ float g_Q[NN * 64];              // n @ Wc1[128:] + bc1

// ---------------- packed f32x2 helpers ----------------
__device__ __forceinline__ unsigned long long pack2(float lo, float hi) {
    unsigned long long r;
    asm("mov.b64 %0, {%1, %2};" : "=l"(r) : "f"(lo), "f"(hi));
    return r;
}
__device__ __forceinline__ void unpack2(unsigned long long v, float& lo, float& hi) {
    asm("mov.b64 {%0, %1}, %2;" : "=f"(lo), "=f"(hi) : "l"(v));
}
__device__ __forceinline__ unsigned long long fma2(unsigned long long a,
                                                   unsigned long long b,
                                                   unsigned long long c) {
    unsigned long long d;
    asm("fma.rn.f32x2 %0, %1, %2, %3;" : "=l"(d) : "l"(a), "l"(b), "l"(c));
    return d;
}
__device__ __forceinline__ float tanh_fast(float x) {
    float y;
    asm("tanh.approx.f32 %0, %1;" : "=f"(y) : "f"(x));
    return y;
}

// fast atan2: Hastings 5-term poly on min/max ratio, max err ~1e-5 rad
__device__ __forceinline__ float atan2_fast(float y, float x) {
    float ax = fabsf(x), ay = fabsf(y);
    float mx = fmaxf(ax, ay), mn = fminf(ax, ay);
    float a = __fdividef(mn, mx);
    float s = a * a;
    float r = fmaf(fmaf(fmaf(fmaf(0.0208351f, s, -0.0851330f), s,
                             0.1801410f), s, -0.3302995f), s, 0.9998660f);
    r = r * a;
    if (ay > ax) r = 1.5707963267948966f - r;
    if (x < 0.f) r = 3.14159265358979323f - r;
    return (y < 0.f) ? -r : r;
}

// ---------------- cp.async helpers ----------------
__device__ __forceinline__ uint32_t smem_u32(const void* p) {
    return (uint32_t)__cvta_generic_to_shared(p);
}
__device__ __forceinline__ void cp16(uint32_t s, const void* g) {
    asm volatile("cp.async.cg.shared.global [%0], [%1], 16;" :: "r"(s), "l"(g));
}
__device__ __forceinline__ void cp_commit() {
    asm volatile("cp.async.commit_group;" ::: "memory");
}
__device__ __forceinline__ void cp_wait0() {
    asm volatile("cp.async.wait_group 0;" ::: "memory");
}
__device__ __forceinline__ void cp_wait1() {
    asm volatile("cp.async.wait_group 1;" ::: "memory");
}

// stage one TT x C weight tile into smem buffer (NTHR threads, float4 chunks)
template<int C, int NTHR>
__device__ __forceinline__ void stage_tile(float* buf, const float* __restrict__ W,
                                           int tile, int tid) {
    const float* src = W + (size_t)tile * TT * C;
    uint32_t b = smem_u32(buf);
    constexpr int NV = TT * C / 4;          // float4s per tile
#pragma unroll
    for (int r = 0; r < NV / NTHR; r++) {
        int idx = tid + NTHR * r;
        cp16(b + idx * 16, src + idx * 4);
    }
    cp_commit();
}

// ---------------- K1 (fused): node projector+LN+AB1  |  edge encoder ----------------
// 256 threads. blocks [0,256): node path (NB=2). blocks [256,768): edge, j = bx-256.
__global__ __launch_bounds__(256) void k_pre(
    const float* __restrict__ X,
    const float* __restrict__ W1, const float* __restrict__ b1,
    const float* __restrict__ W2, const float* __restrict__ b2,
    const float* __restrict__ lng, const float* __restrict__ lnb,
    const float* __restrict__ pos,
    const float* __restrict__ We1, const float* __restrict__ be1,
    const float* __restrict__ We2, const float* __restrict__ be2,
    const float* __restrict__ mW, const float* __restrict__ mb)
{
    const int tid = threadIdx.x;
    if (blockIdx.x < 256) {
        __shared__ float xs[2][SD];
        __shared__ float h1[2][ND];
        __shared__ float xs2[2][ND];
        __shared__ __align__(16) float wt[2][TT * ND];
        __shared__ float ssum[2][4], ssq[2][4];

        const int nd = tid >> 7;
        const int k  = tid & 127;
        const int n0 = blockIdx.x * 2;

        for (int idx = tid; idx < 2 * SD; idx += 256)
            xs[idx >> 8][idx & 255] = X[n0 * SD + idx];

        // ---- GEMM1: h1 = relu(xs @ W1 + b1), 8 tiles of 32x128 ----
        stage_tile<ND, 256>(wt[0], W1, 0, tid);
        stage_tile<ND, 256>(wt[1], W1, 1, tid);
        float acc = 0.f;
#pragma unroll
        for (int tile = 0; tile < 8; tile++) {
            const int buf = tile & 1;
            if (tile == 7) cp_wait0(); else cp_wait1();
            __syncthreads();
#pragma unroll
            for (int tt = 0; tt < TT; tt++)
                acc += xs[nd][tile * TT + tt] * wt[buf][tt * ND + k];
            if (tile + 2 < 8) {
                __syncthreads();
                stage_tile<ND, 256>(wt[buf], W1, tile + 2, tid);
            }
        }
        h1[nd][k] = fmaxf(acc + b1[k], 0.f);

        // ---- GEMM2: acc = h1 @ W2 + b2, 4 tiles of 32x128 ----
        stage_tile<ND, 256>(wt[0], W2, 0, tid);
        stage_tile<ND, 256>(wt[1], W2, 1, tid);
        acc = 0.f;
#pragma unroll
        for (int tile = 0; tile < 4; tile++) {
            const int buf = tile & 1;
            if (tile == 3) cp_wait0(); else cp_wait1();
            __syncthreads();          // also orders h1 writes before reads (tile 0)
#pragma unroll
            for (int tt = 0; tt < TT; tt++)
                acc += h1[nd][tile * TT + tt] * wt[buf][tt * ND + k];
            if (tile + 2 < 4) {
                __syncthreads();
                stage_tile<ND, 256>(wt[buf], W2, tile + 2, tid);
            }
        }
        acc += b2[k];

        // wt[0] free (last read at tile 2, barrier passed): prefetch AB tile 0 now
        stage_tile<ND, 256>(wt[0], mW, 0, tid);

        // ---- LayerNorm ----
        const int w4 = (tid >> 5) & 3, lane = tid & 31;
        {
            float v = acc, v2 = v * v;
            for (int o = 16; o > 0; o >>= 1) {
                v  += __shfl_xor_sync(0xffffffffu, v,  o);
                v2 += __shfl_xor_sync(0xffffffffu, v2, o);
            }
            if (lane == 0) { ssum[nd][w4] = v; ssq[nd][w4] = v2; }
        }
        __syncthreads();              // ssum ready; also all reads of wt[1] done
        stage_tile<ND, 256>(wt[1], mW, 1, tid);
        float s = ssum[nd][0] + ssum[nd][1] + ssum[nd][2] + ssum[nd][3];
        float q = ssq[nd][0] + ssq[nd][1] + ssq[nd][2] + ssq[nd][3];
        float mu = s * (1.0f / ND);
        float var = q * (1.0f / ND) - mu * mu;
        float r = rsqrtf(var + 1e-5f);
        float nval = (acc - mu) * r * lng[k] + lnb[k];
        g_n[(n0 + nd) * ND + k] = nval;
        xs2[nd][k] = nval;

        // ---- AB1: A = n@mW[:128], B = n@mW[128:256] + mb, 8 tiles ----
        float accA = 0.f, accB = 0.f;
#pragma unroll
        for (int tile = 0; tile < 8; tile++) {
            const int buf = tile & 1;
            if (tile == 7) cp_wait0(); else cp_wait1();
            __syncthreads();          // tile 0: also publishes xs2
            if (tile < 4) {
#pragma unroll
                for (int tt = 0; tt < TT; tt++)
                    accA += xs2[nd][tile * TT + tt] * wt[buf][tt * ND + k];
            } else {
#pragma unroll
                for (int tt = 0; tt < TT; tt++)
                    accB += xs2[nd][(tile - 4) * TT + tt] * wt[buf][tt * ND + k];
            }
            if (tile + 2 < 8) {
                __syncthreads();
                stage_tile<ND, 256>(wt[buf], mW, tile + 2, tid);
            }
        }
        g_A[(n0 + nd) * ND + k] = accA;
        g_B[(n0 + nd) * ND + k] = accB + mb[k];
    } else {
        // ---- edge encoder: writes natural [j][i][t] layout ----
        __shared__ float w1s[64], b1s[16], w2s[256], b2s[16];
        if (tid < 64) w1s[tid] = We1[tid];
        if (tid < 256) w2s[tid] = We2[tid];
        if (tid < 16) { b1s[tid] = be1[tid]; b2s[tid] = be2[tid]; }

        const int j = blockIdx.x - 256;
        const float pjx = pos[j * 2], pjy = pos[j * 2 + 1];
        __syncthreads();

        for (int i = tid; i < NN; i += 256) {
            float4* o4 = (float4*)&g_ef[((size_t)j * NN + i) * ED];
            if (i == j) {
                float4 z = make_float4(0.f, 0.f, 0.f, 0.f);
#pragma unroll
                for (int r = 0; r < 4; r++) o4[r] = z;
                continue;
            }
            const float pix = pos[i * 2], piy = pos[i * 2 + 1];
            const float dx = pjx - pix, dy = pjy - piy;
            const float dist = sqrtf(dx * dx + dy * dy);
            const float ang = atan2_fast(dy, dx);
            float h[16];
#pragma unroll
            for (int u = 0; u < 16; u++) {
                float a = pix * w1s[u] + piy * w1s[16 + u] + dist * w1s[32 + u]
                        + ang * w1s[48 + u] + b1s[u];
                h[u] = fmaxf(a, 0.f);
            }
            float o[16];
#pragma unroll
            for (int v = 0; v < 16; v++) {
                float a = b2s[v];
#pragma unroll
                for (int u = 0; u < 16; u++) a += h[u] * w2s[u * 16 + v];
                o[v] = tanh_fast(a);
            }
            o4[0] = make_float4(o[0], o[1], o[2], o[3]);
            o4[1] = make_float4(o[4], o[5], o[6], o[7]);
            o4[2] = make_float4(o[8], o[9], o[10], o[11]);
            o4[3] = make_float4(o[12], o[13], o[14], o[15]);
        }
    }
}

// ---------------- K4: fused ef-matvec + relu + segment-sum (partial) ----------------
// block = 128 threads = 2 dst j's (64 threads each); thread owns feature pair
// (2u, 2u+1), one even/odd-t packed chain per feature. ef staged through smem.
// No i!=j predicate in the loop — spurious i==j term equals relu(A[j]+B[j])
// exactly (ef[j,j]=0) and is subtracted afterwards.
// grid = (256 j-pairs, NCH2 i-chunks of CH=64).
__global__ __launch_bounds__(128) void k_agg(const float* __restrict__ mW)
{
    __shared__ __align__(16) float efs[2][CH * ED];   // 2 x 4 KB

    const int grp = threadIdx.x >> 6;       // j within pair
    const int u   = threadIdx.x & 63;       // feature-pair index
    const int j  = blockIdx.x * 2 + grp;
    const int i0 = blockIdx.y * CH;
    const int f  = 2 * u;

    // W pairs: W0[s] = (w[2s][f], w[2s+1][f]),  W1[s] = same for f+1
    unsigned long long W0[8], W1[8];
#pragma unroll
    for (int s = 0; s < 8; s++) {
        W0[s] = pack2(mW[(2 * ND + 2 * s) * ND + f],
                      mW[(2 * ND + 2 * s + 1) * ND + f]);
        W1[s] = pack2(mW[(2 * ND + 2 * s) * ND + f + 1],
                      mW[(2 * ND + 2 * s + 1) * ND + f + 1]);
    }
    const float B0 = g_B[j * ND + f];
    const float B1 = g_B[j * ND + f + 1];

    // stage this group's CH i's of ef (4 KB) — coalesced bulk copy, high MLP
    {
        const float4* src = (const float4*)&g_ef[((size_t)j * NN + i0) * ED];
        float4* dst = (float4*)efs[grp];
#pragma unroll
        for (int r = 0; r < 4; r++)
            dst[u + 64 * r] = src[u + 64 * r];
    }
    __syncthreads();

    float acc0 = 0.f, acc1 = 0.f;
#pragma unroll 2
    for (int ii = 0; ii < CH; ii++) {
        const int i = i0 + ii;
        float2 a = *(const float2*)&g_A[i * ND + f];
        const ulonglong2* ep = (const ulonglong2*)&efs[grp][ii * ED];
        ulonglong2 q0 = ep[0], q1 = ep[1], q2 = ep[2], q3 = ep[3];

        unsigned long long c0 = pack2(a.x + B0, 0.f);
        unsigned long long c1 = pack2(a.y + B1, 0.f);
        c0 = fma2(q0.x, W0[0], c0);  c1 = fma2(q0.x, W1[0], c1);
        c0 = fma2(q0.y, W0[1], c0);  c1 = fma2(q0.y, W1[1], c1);
        c0 = fma2(q1.x, W0[2], c0);  c1 = fma2(q1.x, W1[2], c1);
        c0 = fma2(q1.y, W0[3], c0);  c1 = fma2(q1.y, W1[3], c1);
        c0 = fma2(q2.x, W0[4], c0);  c1 = fma2(q2.x, W1[4], c1);
        c0 = fma2(q2.y, W0[5], c0);  c1 = fma2(q2.y, W1[5], c1);
        c0 = fma2(q3.x, W0[6], c0);  c1 = fma2(q3.x, W1[6], c1);
        c0 = fma2(q3.y, W0[7], c0);  c1 = fma2(q3.y, W1[7], c1);

        float l0, h0, l1, h1;
        unpack2(c0, l0, h0);
        unpack2(c1, l1, h1);
        acc0 += fmaxf(l0 + h0, 0.f);
        acc1 += fmaxf(l1 + h1, 0.f);
    }

    // remove the spurious i==j contribution (exactly relu(A[j]+B[j]))
    if (j >= i0 && j < i0 + CH) {
        float2 aj = *(const float2*)&g_A[j * ND + f];
        acc0 -= fmaxf(aj.x + B0, 0.f);
        acc1 -= fmaxf(aj.y + B1, 0.f);
    }
    *(float2*)&g_aggp[blockIdx.y][j * ND + f] = make_float2(acc0, acc1);
}

// ---------------- K5a: upd (layer 1) fused with AB2 ----------------
// 512 threads, NB=4 nodes/block, 128 blocks.
__global__ __launch_bounds__(512) void k_upd_ab(
    const float* __restrict__ nin,
    const float* __restrict__ uW, const float* __restrict__ ub,
    float* __restrict__ nout,
    const float* __restrict__ mW, const float* __restrict__ mb)
{
    __shared__ float xs[4][2 * ND];
    __shared__ float xs2[4][ND];
    __shared__ __align__(16) float wt[2][TT * ND];
    const int tid = threadIdx.x;
    const int nd = tid >> 7;
    const int k  = tid & 127;
    const int n0 = blockIdx.x * 4;

    {
        int off = (n0 + nd) * ND + k;
        float s = g_aggp[0][off];
#pragma unroll
        for (int c = 1; c < NCH2; c++) s += g_aggp[c][off];
        xs[nd][k]      = nin[off];
        xs[nd][ND + k] = s;
    }

    stage_tile<ND, 512>(wt[0], uW, 0, tid);
    stage_tile<ND, 512>(wt[1], uW, 1, tid);

    float acc = 0.f;
#pragma unroll
    for (int tile = 0; tile < 8; tile++) {
        const int buf = tile & 1;
        if (tile == 7) cp_wait0(); else cp_wait1();
        __syncthreads();
#pragma unroll
        for (int tt = 0; tt < TT; tt++)
            acc += xs[nd][tile * TT + tt] * wt[buf][tt * ND + k];
        if (tile + 2 < 8) {
            __syncthreads();
            stage_tile<ND, 512>(wt[buf], uW, tile + 2, tid);
        }
    }
    float nval = fmaxf(acc + ub[k], 0.f);
    nout[(n0 + nd) * ND + k] = nval;
    xs2[nd][k] = nval;

    // wt[0] free (last read tile 6, barrier passed at tile 7's top)
    stage_tile<ND, 512>(wt[0], mW, 0, tid);
    __syncthreads();                       // all done reading wt[1]; xs2 published
    stage_tile<ND, 512>(wt[1], mW, 1, tid);

    // ---- AB2 ----
    float accA = 0.f, accB = 0.f;
#pragma unroll
    for (int tile = 0; tile < 8; tile++) {
        const int buf = tile & 1;
        if (tile == 7) cp_wait0(); else cp_wait1();
        __syncthreads();
        if (tile < 4) {
#pragma unroll
            for (int tt = 0; tt < TT; tt++)
                accA += xs2[nd][tile * TT + tt] * wt[buf][tt * ND + k];
        } else {
#pragma unroll
            for (int tt = 0; tt < TT; tt++)
                accB += xs2[nd][(tile - 4) * TT + tt] * wt[buf][tt * ND + k];
        }
        if (tile + 2 < 8) {
            __syncthreads();
            stage_tile<ND, 512>(wt[buf], mW, tile + 2, tid);
        }
    }
    g_A[(n0 + nd) * ND + k] = accA;
    g_B[(n0 + nd) * ND + k] = accB + mb[k];
}

// ---------------- K5b: upd (layer 2) fused with P/Q classifier GEMM ----------------
// 512 threads, NB=4 nodes/block, 128 blocks. P/Q tiles staged as pairs so both
// thread-halves stay busy.
__global__ __launch_bounds__(512) void k_upd_pq(
    const float* __restrict__ nin,
    const float* __restrict__ uW, const float* __restrict__ ub,
    float* __restrict__ nout,
    const float* __restrict__ Wc1, const float* __restrict__ bc1)
{
    __shared__ float xs[4][2 * ND];
    __shared__ float xs2[4][ND];
    __shared__ __align__(16) float wt[2][TT * ND];   // reused as [2][2][TT*64] for PQ
    const int tid = threadIdx.x;
    const int nd = tid >> 7;
    const int k  = tid & 127;
    const int n0 = blockIdx.x * 4;

    {
        int off = (n0 + nd) * ND + k;
        float s = g_aggp[0][off];
#pragma unroll
        for (int c = 1; c < NCH2; c++) s += g_aggp[c][off];
        xs[nd][k]      = nin[off];
        xs[nd][ND + k] = s;
    }

    stage_tile<ND, 512>(wt[0], uW, 0, tid);
    stage_tile<ND, 512>(wt[1], uW, 1, tid);

    float acc = 0.f;
#pragma unroll
    for (int tile = 0; tile < 8; tile++) {
        const int buf = tile & 1;
        if (tile == 7) cp_wait0(); else cp_wait1();
        __syncthreads();
#pragma unroll
        for (int tt = 0; tt < TT; tt++)
            acc += xs[nd][tile * TT + tt] * wt[buf][tt * ND + k];
        if (tile + 2 < 8) {
            __syncthreads();
            stage_tile<ND, 512>(wt[buf], uW, tile + 2, tid);
        }
    }
    float nval = fmaxf(acc + ub[k], 0.f);
    nout[(n0 + nd) * ND + k] = nval;
    xs2[nd][k] = nval;

    // ---- PQ: stage P-tile + Q-tile pairs (16KB each phase, 4 phases) ----
    {
        uint32_t b0 = smem_u32(wt[0]);
        cp16(b0 + tid * 16, Wc1 + 0 * TT * 64 + tid * 4);                 // P rows 0-31
        cp16(b0 + 8192 + tid * 16, Wc1 + (128 + 0 * TT) * 64 + tid * 4);  // Q rows 128-159
        cp_commit();
    }
    __syncthreads();                       // wt[1] free; xs2 published
    {
        uint32_t b1 = smem_u32(wt[1]);
        cp16(b1 + tid * 16, Wc1 + 1 * TT * 64 + tid * 4);
        cp16(b1 + 8192 + tid * 16, Wc1 + (128 + 1 * TT) * 64 + tid * 4);
        cp_commit();
    }

    const int half = (k >> 6);             // 0 -> P, 1 -> Q
    const int k64  = k & 63;
    float accPQ = 0.f;
#pragma unroll
    for (int phase = 0; phase < 4; phase++) {
        const int buf = phase & 1;
        if (phase == 3) cp_wait0(); else cp_wait1();
        __syncthreads();
        const float* w = &wt[buf][half * 2048];
#pragma unroll
        for (int tt = 0; tt < TT; tt++)
            accPQ += xs2[nd][phase * TT + tt] * w[tt * 64 + k64];
        if (phase + 2 < 4) {
            __syncthreads();
            uint32_t b = smem_u32(wt[buf]);
            cp16(b + tid * 16, Wc1 + (phase + 2) * TT * 64 + tid * 4);
            cp16(b + 8192 + tid * 16, Wc1 + (128 + (phase + 2) * TT) * 64 + tid * 4);
            cp_commit();
        }
    }
    if (half) g_Q[(n0 + nd) * 64 + k64] = accPQ + bc1[k64];
    else      g_P[(n0 + nd) * 64 + k64] = accPQ;
}

// ---------------- K7: pairwise scores (relu(P_i+Q_j) @ Wc2 -> sigmoid) ----------------
__global__ __launch_bounds__(256) void k_scores(
    const float* __restrict__ Wc2, const float* __restrict__ bc2,
    float* __restrict__ out)
{
    __shared__ float Ps[16][65], Qs[16][65], ws[64];
    const int tid = threadIdx.x;
    const int tx = tid & 15, ty = tid >> 4;
    const int j0 = blockIdx.x * 16, i0 = blockIdx.y * 16;

    for (int idx = tid; idx < 16 * 64; idx += 256) {
        int r = idx >> 6, c = idx & 63;
        Ps[r][c] = g_P[(i0 + r) * 64 + c];
        Qs[r][c] = g_Q[(j0 + r) * 64 + c];
    }
    if (tid < 64) ws[tid] = Wc2[tid];
    __syncthreads();

    float acc = 0.f;
#pragma unroll 8
    for (int t = 0; t < 64; t++)
        acc += fmaxf(Ps[ty][t] + Qs[tx][t], 0.f) * ws[t];
    acc += bc2[0];
    float s = 1.f / (1.f + expf(-acc));
    const int i = i0 + ty, j = j0 + tx;
    out[i * NN + j] = (i == j) ? 0.f : s;
}

// ---------------- launch ----------------
extern "C" void kernel_launch(void* const* d_in, const int* in_sizes, int n_in,
                              void* d_out, int out_size)
{
    const float* X   = (const float*)d_in[0];
    const float* pos = (const float*)d_in[1];
    const float* W1  = (const float*)d_in[2];
    const float* b1  = (const float*)d_in[3];
    const float* W2  = (const float*)d_in[4];
    const float* b2  = (const float*)d_in[5];
    const float* lng = (const float*)d_in[6];
    const float* lnb = (const float*)d_in[7];
    const float* We1 = (const float*)d_in[8];
    const float* be1 = (const float*)d_in[9];
    const float* We2 = (const float*)d_in[10];
    const float* be2 = (const float*)d_in[11];
    const float* mW1 = (const float*)d_in[12];
    const float* mb1 = (const float*)d_in[13];
    const float* uW1 = (const float*)d_in[14];
    const float* ub1 = (const float*)d_in[15];
    const float* mW2 = (const float*)d_in[16];
    const float* mb2 = (const float*)d_in[17];
    const float* uW2 = (const float*)d_in[18];
    const float* ub2 = (const float*)d_in[19];
    const float* Wc1 = (const float*)d_in[20];
    const float* bc1 = (const float*)d_in[21];
    const float* Wc2 = (const float*)d_in[22];
    const float* bc2 = (const float*)d_in[23];

    float* out   = (float*)d_out;
    float* out_n = out;             // [512*128] node features
    float* out_s = out + NN * ND;   // [512*512] scores

    float *pN = nullptr, *pN2 = nullptr;
    cudaGetSymbolAddress((void**)&pN,  g_n);
    cudaGetSymbolAddress((void**)&pN2, g_n2);

    // node projector+LN+AB1 (blocks 0..255) + edge encoder (blocks 256..767)
    k_pre<<<768, 256>>>(X, W1, b1, W2, b2, lng, lnb,
                        pos, We1, be1, We2, be2, mW1, mb1);

    // MPN layer 1 (agg) then fused update+AB2
    k_agg<<<dim3(256, NCH2), 128>>>(mW1);
    k_upd_ab<<<128, 512>>>(pN, uW1, ub1, pN2, mW2, mb2);

    // MPN layer 2 (agg) then fused update+PQ (final node features -> d_out)
    k_agg<<<dim3(256, NCH2), 128>>>(mW2);
    k_upd_pq<<<128, 512>>>(pN2, uW2, ub2, out_n, Wc1, bc1);

    // pairwise scores
    k_scores<<<dim3(32, 32), 256>>>(Wc2, bc2, out_s);
}

// round 15
// speedup vs baseline: 1.0904x; 1.0393x over previous
#include <cuda_runtime.h>
#include <cstdint>
#include <cstddef>

// Problem constants
#define NN 512
#define SD 256
#define ND 128
#define ED 16
#define CH 64               // i's per chunk in k_agg
#define NCH2 (NN / CH)      // 8 chunks
#define TT 32               // weight-tile rows for cp.async GEMMs

// ---------------- scratch (static device globals; no allocation) ----------------
__device__ float g_ef[NN * NN * ED];        // edge features, natural: [j][i][t] (16.7 MB)
__device__ float g_n[NN * ND];              // node features after projector+LN
__device__ float g_n2[NN * ND];             // node features after MPN layer 1
__device__ float g_A[NN * ND];              // n @ mW_src
__device__ float g_B[NN * ND];              // n @ mW_dst + mb
__device__ float g_aggp[NCH2][NN * ND];     // partial aggregated messages (per i-chunk)
__device__ float g_P[NN * 64];              // n @ Wc1[:128]
__device__ float g_Q[NN * 64];              // n @ Wc1[128:] + bc1

// ---------------- packed f32x2 helpers ----------------
__device__ __forceinline__ unsigned long long pack2(float lo, float hi) {
    unsigned long long r;
    asm("mov.b64 %0, {%1, %2};" : "=l"(r) : "f"(lo), "f"(hi));
    return r;
}
__device__ __forceinline__ void unpack2(unsigned long long v, float& lo, float& hi) {
    asm("mov.b64 {%0, %1}, %2;" : "=f"(lo), "=f"(hi) : "l"(v));
}
__device__ __forceinline__ unsigned long long fma2(unsigned long long a,
                                                   unsigned long long b,
                                                   unsigned long long c) {
    unsigned long long d;
    asm("fma.rn.f32x2 %0, %1, %2, %3;" : "=l"(d) : "l"(a), "l"(b), "l"(c));
    return d;
}
__device__ __forceinline__ float tanh_fast(float x) {
    float y;
    asm("tanh.approx.f32 %0, %1;" : "=f"(y) : "f"(x));
    return y;
}

// fast atan2: Hastings 5-term poly on min/max ratio, max err ~1e-5 rad
__device__ __forceinline__ float atan2_fast(float y, float x) {
    float ax = fabsf(x), ay = fabsf(y);
    float mx = fmaxf(ax, ay), mn = fminf(ax, ay);
    float a = __fdividef(mn, mx);
    float s = a * a;
    float r = fmaf(fmaf(fmaf(fmaf(0.0208351f, s, -0.0851330f), s,
                             0.1801410f), s, -0.3302995f), s, 0.9998660f);
    r = r * a;
    if (ay > ax) r = 1.5707963267948966f - r;
    if (x < 0.f) r = 3.14159265358979323f - r;
    return (y < 0.f) ? -r : r;
}

// ---------------- cp.async helpers ----------------
__device__ __forceinline__ uint32_t smem_u32(const void* p) {
    return (uint32_t)__cvta_generic_to_shared(p);
}
__device__ __forceinline__ void cp16(uint32_t s, const void* g) {
    asm volatile("cp.async.cg.shared.global [%0], [%1], 16;" :: "r"(s), "l"(g));
}
__device__ __forceinline__ void cp_commit() {
    asm volatile("cp.async.commit_group;" ::: "memory");
}
__device__ __forceinline__ void cp_wait0() {
    asm volatile("cp.async.wait_group 0;" ::: "memory");
}
__device__ __forceinline__ void cp_wait1() {
    asm volatile("cp.async.wait_group 1;" ::: "memory");
}

// stage one TT x C weight tile into smem buffer (NTHR threads, float4 chunks)
template<int C, int NTHR>
__device__ __forceinline__ void stage_tile(float* buf, const float* __restrict__ W,
                                           int tile, int tid) {
    const float* src = W + (size_t)tile * TT * C;
    uint32_t b = smem_u32(buf);
    constexpr int NV = TT * C / 4;          // float4s per tile
#pragma unroll
    for (int r = 0; r < NV / NTHR; r++) {
        int idx = tid + NTHR * r;
        cp16(b + idx * 16, src + idx * 4);
    }
    cp_commit();
}

// ---------------- K1 (fused): node projector+LN+AB1  |  edge encoder ----------------
// 256 threads. blocks [0,256): node path (NB=2). blocks [256,768): edge, j = bx-256.
__global__ __launch_bounds__(256) void k_pre(
    const float* __restrict__ X,
    const float* __restrict__ W1, const float* __restrict__ b1,
    const float* __restrict__ W2, const float* __restrict__ b2,
    const float* __restrict__ lng, const float* __restrict__ lnb,
    const float* __restrict__ pos,
    const float* __restrict__ We1, const float* __restrict__ be1,
    const float* __restrict__ We2, const float* __restrict__ be2,
    const float* __restrict__ mW, const float* __restrict__ mb)
{
    const int tid = threadIdx.x;
    if (blockIdx.x < 256) {
        __shared__ float xs[2][SD];
        __shared__ float h1[2][ND];
        __shared__ float xs2[2][ND];
        __shared__ __align__(16) float wt[2][TT * ND];
        __shared__ float ssum[2][4], ssq[2][4];

        const int nd = tid >> 7;
        const int k  = tid & 127;
        const int n0 = blockIdx.x * 2;

        for (int idx = tid; idx < 2 * SD; idx += 256)
            xs[idx >> 8][idx & 255] = X[n0 * SD + idx];

        // ---- GEMM1: h1 = relu(xs @ W1 + b1), 8 tiles of 32x128 ----
        stage_tile<ND, 256>(wt[0], W1, 0, tid);
        stage_tile<ND, 256>(wt[1], W1, 1, tid);
        float acc = 0.f;
#pragma unroll
        for (int tile = 0; tile < 8; tile++) {
            const int buf = tile & 1;
            if (tile == 7) cp_wait0(); else cp_wait1();
            __syncthreads();
#pragma unroll
            for (int tt = 0; tt < TT; tt++)
                acc += xs[nd][tile * TT + tt] * wt[buf][tt * ND + k];
            if (tile + 2 < 8) {
                __syncthreads();
                stage_tile<ND, 256>(wt[buf], W1, tile + 2, tid);
            }
        }
        h1[nd][k] = fmaxf(acc + b1[k], 0.f);

        // ---- GEMM2: acc = h1 @ W2 + b2, 4 tiles of 32x128 ----
        stage_tile<ND, 256>(wt[0], W2, 0, tid);
        stage_tile<ND, 256>(wt[1], W2, 1, tid);
        acc = 0.f;
#pragma unroll
        for (int tile = 0; tile < 4; tile++) {
            const int buf = tile & 1;
            if (tile == 3) cp_wait0(); else cp_wait1();
            __syncthreads();          // also orders h1 writes before reads (tile 0)
#pragma unroll
            for (int tt = 0; tt < TT; tt++)
                acc += h1[nd][tile * TT + tt] * wt[buf][tt * ND + k];
            if (tile + 2 < 4) {
                __syncthreads();
                stage_tile<ND, 256>(wt[buf], W2, tile + 2, tid);
            }
        }
        acc += b2[k];

        // wt[0] free (last read at tile 2, barrier passed): prefetch AB tile 0 now
        stage_tile<ND, 256>(wt[0], mW, 0, tid);

        // ---- LayerNorm ----
        const int w4 = (tid >> 5) & 3, lane = tid & 31;
        {
            float v = acc, v2 = v * v;
            for (int o = 16; o > 0; o >>= 1) {
                v  += __shfl_xor_sync(0xffffffffu, v,  o);
                v2 += __shfl_xor_sync(0xffffffffu, v2, o);
            }
            if (lane == 0) { ssum[nd][w4] = v; ssq[nd][w4] = v2; }
        }
        __syncthreads();              // ssum ready; also all reads of wt[1] done
        stage_tile<ND, 256>(wt[1], mW, 1, tid);
        float s = ssum[nd][0] + ssum[nd][1] + ssum[nd][2] + ssum[nd][3];
        float q = ssq[nd][0] + ssq[nd][1] + ssq[nd][2] + ssq[nd][3];
        float mu = s * (1.0f / ND);
        float var = q * (1.0f / ND) - mu * mu;
        float r = rsqrtf(var + 1e-5f);
        float nval = (acc - mu) * r * lng[k] + lnb[k];
        g_n[(n0 + nd) * ND + k] = nval;
        xs2[nd][k] = nval;

        // ---- AB1: A = n@mW[:128], B = n@mW[128:256] + mb, 8 tiles ----
        float accA = 0.f, accB = 0.f;
#pragma unroll
        for (int tile = 0; tile < 8; tile++) {
            const int buf = tile & 1;
            if (tile == 7) cp_wait0(); else cp_wait1();
            __syncthreads();          // tile 0: also publishes xs2
            if (tile < 4) {
#pragma unroll
                for (int tt = 0; tt < TT; tt++)
                    accA += xs2[nd][tile * TT + tt] * wt[buf][tt * ND + k];
            } else {
#pragma unroll
                for (int tt = 0; tt < TT; tt++)
                    accB += xs2[nd][(tile - 4) * TT + tt] * wt[buf][tt * ND + k];
            }
            if (tile + 2 < 8) {
                __syncthreads();
                stage_tile<ND, 256>(wt[buf], mW, tile + 2, tid);
            }
        }
        g_A[(n0 + nd) * ND + k] = accA;
        g_B[(n0 + nd) * ND + k] = accB + mb[k];
    } else {
        // ---- edge encoder: writes natural [j][i][t] layout ----
        __shared__ float w1s[64], b1s[16], w2s[256], b2s[16];
        if (tid < 64) w1s[tid] = We1[tid];
        if (tid < 256) w2s[tid] = We2[tid];
        if (tid < 16) { b1s[tid] = be1[tid]; b2s[tid] = be2[tid]; }

        const int j = blockIdx.x - 256;
        const float pjx = pos[j * 2], pjy = pos[j * 2 + 1];
        __syncthreads();

        for (int i = tid; i < NN; i += 256) {
            float4* o4 = (float4*)&g_ef[((size_t)j * NN + i) * ED];
            if (i == j) {
                float4 z = make_float4(0.f, 0.f, 0.f, 0.f);
#pragma unroll
                for (int r = 0; r < 4; r++) o4[r] = z;
                continue;
            }
            const float pix = pos[i * 2], piy = pos[i * 2 + 1];
            const float dx = pjx - pix, dy = pjy - piy;
            const float dist = sqrtf(dx * dx + dy * dy);
            const float ang = atan2_fast(dy, dx);
            float h[16];
#pragma unroll
            for (int u = 0; u < 16; u++) {
                float a = pix * w1s[u] + piy * w1s[16 + u] + dist * w1s[32 + u]
                        + ang * w1s[48 + u] + b1s[u];
                h[u] = fmaxf(a, 0.f);
            }
            float o[16];
#pragma unroll
            for (int v = 0; v < 16; v++) {
                float a = b2s[v];
#pragma unroll
                for (int u = 0; u < 16; u++) a += h[u] * w2s[u * 16 + v];
                o[v] = tanh_fast(a);
            }
            o4[0] = make_float4(o[0], o[1], o[2], o[3]);
            o4[1] = make_float4(o[4], o[5], o[6], o[7]);
            o4[2] = make_float4(o[8], o[9], o[10], o[11]);
            o4[3] = make_float4(o[12], o[13], o[14], o[15]);
        }
    }
}

// ---------------- K4: fused ef-matvec + relu + segment-sum (partial) ----------------
// block = 256 threads = 4 dst j's (64 threads each) sharing ONE i-chunk.
// thread owns feature pair (2u, 2u+1), one even/odd-t packed chain per feature.
// ef staged per-group (4KB each); the A-chunk (64 i x 128 feat = 32KB) is staged
// ONCE per block and shared by all 4 groups -> inner loop is pure LDS.
// No i!=j predicate in the loop (exact post-loop correction, ef[j,j]=0).
// grid = (128 j-quads, NCH2 i-chunks of CH=64).
__global__ __launch_bounds__(256) void k_agg(const float* __restrict__ mW)
{
    __shared__ __align__(16) float efs[4][CH * ED];   // 16 KB
    __shared__ __align__(16) float as[CH * ND];       // 32 KB

    const int tid = threadIdx.x;
    const int grp = tid >> 6;               // j within quad
    const int u   = tid & 63;               // feature-pair index
    const int j  = blockIdx.x * 4 + grp;
    const int i0 = blockIdx.y * CH;
    const int f  = 2 * u;

    // W pairs: W0[s] = (w[2s][f], w[2s+1][f]),  W1[s] = same for f+1
    unsigned long long W0[8], W1[8];
#pragma unroll
    for (int s = 0; s < 8; s++) {
        W0[s] = pack2(mW[(2 * ND + 2 * s) * ND + f],
                      mW[(2 * ND + 2 * s + 1) * ND + f]);
        W1[s] = pack2(mW[(2 * ND + 2 * s) * ND + f + 1],
                      mW[(2 * ND + 2 * s + 1) * ND + f + 1]);
    }
    const float B0 = g_B[j * ND + f];
    const float B1 = g_B[j * ND + f + 1];

    // stage shared A chunk (32 KB): 2048 float4, 256 threads x 8 — coalesced
    {
        const float4* srcA = (const float4*)&g_A[i0 * ND];
        float4* dstA = (float4*)as;
#pragma unroll
        for (int r = 0; r < 8; r++)
            dstA[tid + 256 * r] = srcA[tid + 256 * r];
    }
    // stage this group's ef chunk (4 KB): 256 float4, 64 threads x 4 — coalesced
    {
        const float4* src = (const float4*)&g_ef[((size_t)j * NN + i0) * ED];
        float4* dst = (float4*)efs[grp];
#pragma unroll
        for (int r = 0; r < 4; r++)
            dst[u + 64 * r] = src[u + 64 * r];
    }
    __syncthreads();

    float acc0 = 0.f, acc1 = 0.f;
#pragma unroll 2
    for (int ii = 0; ii < CH; ii++) {
        float2 a = *(const float2*)&as[ii * ND + f];
        const ulonglong2* ep = (const ulonglong2*)&efs[grp][ii * ED];
        ulonglong2 q0 = ep[0], q1 = ep[1], q2 = ep[2], q3 = ep[3];

        unsigned long long c0 = pack2(a.x + B0, 0.f);
        unsigned long long c1 = pack2(a.y + B1, 0.f);
        c0 = fma2(q0.x, W0[0], c0);  c1 = fma2(q0.x, W1[0], c1);
        c0 = fma2(q0.y, W0[1], c0);  c1 = fma2(q0.y, W1[1], c1);
        c0 = fma2(q1.x, W0[2], c0);  c1 = fma2(q1.x, W1[2], c1);
        c0 = fma2(q1.y, W0[3], c0);  c1 = fma2(q1.y, W1[3], c1);
        c0 = fma2(q2.x, W0[4], c0);  c1 = fma2(q2.x, W1[4], c1);
        c0 = fma2(q2.y, W0[5], c0);  c1 = fma2(q2.y, W1[5], c1);
        c0 = fma2(q3.x, W0[6], c0);  c1 = fma2(q3.x, W1[6], c1);
        c0 = fma2(q3.y, W0[7], c0);  c1 = fma2(q3.y, W1[7], c1);

        float l0, h0, l1, h1;
        unpack2(c0, l0, h0);
        unpack2(c1, l1, h1);
        acc0 += fmaxf(l0 + h0, 0.f);
        acc1 += fmaxf(l1 + h1, 0.f);
    }

    // remove the spurious i==j contribution (exactly relu(A[j]+B[j]))
    if (j >= i0 && j < i0 + CH) {
        float2 aj = *(const float2*)&as[(j - i0) * ND + f];
        acc0 -= fmaxf(aj.x + B0, 0.f);
        acc1 -= fmaxf(aj.y + B1, 0.f);
    }
    *(float2*)&g_aggp[blockIdx.y][j * ND + f] = make_float2(acc0, acc1);
}

// ---------------- K5a: upd (layer 1) fused with AB2 ----------------
// 512 threads, NB=4 nodes/block, 128 blocks.
__global__ __launch_bounds__(512) void k_upd_ab(
    const float* __restrict__ nin,
    const float* __restrict__ uW, const float* __restrict__ ub,
    float* __restrict__ nout,
    const float* __restrict__ mW, const float* __restrict__ mb)
{
    __shared__ float xs[4][2 * ND];
    __shared__ float xs2[4][ND];
    __shared__ __align__(16) float wt[2][TT * ND];
    const int tid = threadIdx.x;
    const int nd = tid >> 7;
    const int k  = tid & 127;
    const int n0 = blockIdx.x * 4;

    {
        int off = (n0 + nd) * ND + k;
        float s = g_aggp[0][off];
#pragma unroll
        for (int c = 1; c < NCH2; c++) s += g_aggp[c][off];
        xs[nd][k]      = nin[off];
        xs[nd][ND + k] = s;
    }

    stage_tile<ND, 512>(wt[0], uW, 0, tid);
    stage_tile<ND, 512>(wt[1], uW, 1, tid);

    float acc = 0.f;
#pragma unroll
    for (int tile = 0; tile < 8; tile++) {
        const int buf = tile & 1;
        if (tile == 7) cp_wait0(); else cp_wait1();
        __syncthreads();
#pragma unroll
        for (int tt = 0; tt < TT; tt++)
            acc += xs[nd][tile * TT + tt] * wt[buf][tt * ND + k];
        if (tile + 2 < 8) {
            __syncthreads();
            stage_tile<ND, 512>(wt[buf], uW, tile + 2, tid);
        }
    }
    float nval = fmaxf(acc + ub[k], 0.f);
    nout[(n0 + nd) * ND + k] = nval;
    xs2[nd][k] = nval;

    // wt[0] free (last read tile 6, barrier passed at tile 7's top)
    stage_tile<ND, 512>(wt[0], mW, 0, tid);
    __syncthreads();                       // all done reading wt[1]; xs2 published
    stage_tile<ND, 512>(wt[1], mW, 1, tid);

    // ---- AB2 ----
    float accA = 0.f, accB = 0.f;
#pragma unroll
    for (int tile = 0; tile < 8; tile++) {
        const int buf = tile & 1;
        if (tile == 7) cp_wait0(); else cp_wait1();
        __syncthreads();
        if (tile < 4) {
#pragma unroll
            for (int tt = 0; tt < TT; tt++)
                accA += xs2[nd][tile * TT + tt] * wt[buf][tt * ND + k];
        } else {
#pragma unroll
            for (int tt = 0; tt < TT; tt++)
                accB += xs2[nd][(tile - 4) * TT + tt] * wt[buf][tt * ND + k];
        }
        if (tile + 2 < 8) {
            __syncthreads();
            stage_tile<ND, 512>(wt[buf], mW, tile + 2, tid);
        }
    }
    g_A[(n0 + nd) * ND + k] = accA;
    g_B[(n0 + nd) * ND + k] = accB + mb[k];
}

// ---------------- K5b: upd (layer 2) fused with P/Q classifier GEMM ----------------
// 512 threads, NB=4 nodes/block, 128 blocks. P/Q tiles staged as pairs so both
// thread-halves stay busy.
__global__ __launch_bounds__(512) void k_upd_pq(
    const float* __restrict__ nin,
    const float* __restrict__ uW, const float* __restrict__ ub,
    float* __restrict__ nout,
    const float* __restrict__ Wc1, const float* __restrict__ bc1)
{
    __shared__ float xs[4][2 * ND];
    __shared__ float xs2[4][ND];
    __shared__ __align__(16) float wt[2][TT * ND];   // reused as [2][2][TT*64] for PQ
    const int tid = threadIdx.x;
    const int nd = tid >> 7;
    const int k  = tid & 127;
    const int n0 = blockIdx.x * 4;

    {
        int off = (n0 + nd) * ND + k;
        float s = g_aggp[0][off];
#pragma unroll
        for (int c = 1; c < NCH2; c++) s += g_aggp[c][off];
        xs[nd][k]      = nin[off];
        xs[nd][ND + k] = s;
    }

    stage_tile<ND, 512>(wt[0], uW, 0, tid);
    stage_tile<ND, 512>(wt[1], uW, 1, tid);

    float acc = 0.f;
#pragma unroll
    for (int tile = 0; tile < 8; tile++) {
        const int buf = tile & 1;
        if (tile == 7) cp_wait0(); else cp_wait1();
        __syncthreads();
#pragma unroll
        for (int tt = 0; tt < TT; tt++)
            acc += xs[nd][tile * TT + tt] * wt[buf][tt * ND + k];
        if (tile + 2 < 8) {
            __syncthreads();
            stage_tile<ND, 512>(wt[buf], uW, tile + 2, tid);
        }
    }
    float nval = fmaxf(acc + ub[k], 0.f);
    nout[(n0 + nd) * ND + k] = nval;
    xs2[nd][k] = nval;

    // ---- PQ: stage P-tile + Q-tile pairs (16KB each phase, 4 phases) ----
    {
        uint32_t b0 = smem_u32(wt[0]);
        cp16(b0 + tid * 16, Wc1 + 0 * TT * 64 + tid * 4);                 // P rows 0-31
        cp16(b0 + 8192 + tid * 16, Wc1 + (128 + 0 * TT) * 64 + tid * 4);  // Q rows 128-159
        cp_commit();
    }
    __syncthreads();                       // wt[1] free; xs2 published
    {
        uint32_t b1 = smem_u32(wt[1]);
        cp16(b1 + tid * 16, Wc1 + 1 * TT * 64 + tid * 4);
        cp16(b1 + 8192 + tid * 16, Wc1 + (128 + 1 * TT) * 64 + tid * 4);
        cp_commit();
    }

    const int half = (k >> 6);             // 0 -> P, 1 -> Q
    const int k64  = k & 63;
    float accPQ = 0.f;
#pragma unroll
    for (int phase = 0; phase < 4; phase++) {
        const int buf = phase & 1;
        if (phase == 3) cp_wait0(); else cp_wait1();
        __syncthreads();
        const float* w = &wt[buf][half * 2048];
#pragma unroll
        for (int tt = 0; tt < TT; tt++)
            accPQ += xs2[nd][phase * TT + tt] * w[tt * 64 + k64];
        if (phase + 2 < 4) {
            __syncthreads();
            uint32_t b = smem_u32(wt[buf]);
            cp16(b + tid * 16, Wc1 + (phase + 2) * TT * 64 + tid * 4);
            cp16(b + 8192 + tid * 16, Wc1 + (128 + (phase + 2) * TT) * 64 + tid * 4);
            cp_commit();
        }
    }
    if (half) g_Q[(n0 + nd) * 64 + k64] = accPQ + bc1[k64];
    else      g_P[(n0 + nd) * 64 + k64] = accPQ;
}

// ---------------- K7: pairwise scores (relu(P_i+Q_j) @ Wc2 -> sigmoid) ----------------
__global__ __launch_bounds__(256) void k_scores(
    const float* __restrict__ Wc2, const float* __restrict__ bc2,
    float* __restrict__ out)
{
    __shared__ float Ps[16][65], Qs[16][65], ws[64];
    const int tid = threadIdx.x;
    const int tx = tid & 15, ty = tid >> 4;
    const int j0 = blockIdx.x * 16, i0 = blockIdx.y * 16;

    for (int idx = tid; idx < 16 * 64; idx += 256) {
        int r = idx >> 6, c = idx & 63;
        Ps[r][c] = g_P[(i0 + r) * 64 + c];
        Qs[r][c] = g_Q[(j0 + r) * 64 + c];
    }
    if (tid < 64) ws[tid] = Wc2[tid];
    __syncthreads();

    float acc = 0.f;
#pragma unroll 8
    for (int t = 0; t < 64; t++)
        acc += fmaxf(Ps[ty][t] + Qs[tx][t], 0.f) * ws[t];
    acc += bc2[0];
    float s = 1.f / (1.f + expf(-acc));
    const int i = i0 + ty, j = j0 + tx;
    out[i * NN + j] = (i == j) ? 0.f : s;
}

// ---------------- launch ----------------
extern "C" void kernel_launch(void* const* d_in, const int* in_sizes, int n_in,
                              void* d_out, int out_size)
{
    const float* X   = (const float*)d_in[0];
    const float* pos = (const float*)d_in[1];
    const float* W1  = (const float*)d_in[2];
    const float* b1  = (const float*)d_in[3];
    const float* W2  = (const float*)d_in[4];
    const float* b2  = (const float*)d_in[5];
    const float* lng = (const float*)d_in[6];
    const float* lnb = (const float*)d_in[7];
    const float* We1 = (const float*)d_in[8];
    const float* be1 = (const float*)d_in[9];
    const float* We2 = (const float*)d_in[10];
    const float* be2 = (const float*)d_in[11];
    const float* mW1 = (const float*)d_in[12];
    const float* mb1 = (const float*)d_in[13];
    const float* uW1 = (const float*)d_in[14];
    const float* ub1 = (const float*)d_in[15];
    const float* mW2 = (const float*)d_in[16];
    const float* mb2 = (const float*)d_in[17];
    const float* uW2 = (const float*)d_in[18];
    const float* ub2 = (const float*)d_in[19];
    const float* Wc1 = (const float*)d_in[20];
    const float* bc1 = (const float*)d_in[21];
    const float* Wc2 = (const float*)d_in[22];
    const float* bc2 = (const float*)d_in[23];

    float* out   = (float*)d_out;
    float* out_n = out;             // [512*128] node features
    float* out_s = out + NN * ND;   // [512*512] scores

    float *pN = nullptr, *pN2 = nullptr;
    cudaGetSymbolAddress((void**)&pN,  g_n);
    cudaGetSymbolAddress((void**)&pN2, g_n2);

    // node projector+LN+AB1 (blocks 0..255) + edge encoder (blocks 256..767)
    k_pre<<<768, 256>>>(X, W1, b1, W2, b2, lng, lnb,
                        pos, We1, be1, We2, be2, mW1, mb1);

    // MPN layer 1 (agg) then fused update+AB2
    k_agg<<<dim3(128, NCH2), 256>>>(mW1);
    k_upd_ab<<<128, 512>>>(pN, uW1, ub1, pN2, mW2, mb2);

    // MPN layer 2 (agg) then fused update+PQ (final node features -> d_out)
    k_agg<<<dim3(128, NCH2), 256>>>(mW2);
    k_upd_pq<<<128, 512>>>(pN2, uW2, ub2, out_n, Wc1, bc1);

    // pairwise scores
    k_scores<<<dim3(32, 32), 256>>>(Wc2, bc2, out_s);
}